// round 17
// baseline (speedup 1.0000x reference)
#include <cuda_runtime.h>

#define BB 4
#define CC 32
#define NF 40000
#define NE 80000
#define NV 40000
#define CAP 32          // bucket row = 32 ints = exactly one warp-coalesced load

// cnt layout: [f2e: NE][e2v: NV][ff: NF][e2f: NF][v2e: NE]
#define CNT_TOT (NE + NV + NF + NF + NE)
#define OFF_F2E 0
#define OFF_E2V (NE)
#define OFF_FF  (NE + NV)
#define OFF_E2F (NE + NV + NF)
#define OFF_V2E (NE + NV + NF + NF)

typedef unsigned long long ull;

// Persistent scratch (no allocations anywhere); canonical [b][node][c] layout.
__device__ float g_xf0[BB * NF * CC];
__device__ float g_xe0[BB * NE * CC];
__device__ float g_xv0[BB * NV * CC];
__device__ float g_xe1[BB * NE * CC];   // F2E output
__device__ float g_xf1[BB * NF * CC];   // FF output
__device__ int   g_cnt[CNT_TOT];
__device__ int   g_bucket[(size_t)CNT_TOT * CAP];

__device__ __forceinline__ ull ffma2(ull a, ull b, ull c) {
    ull d;
    asm("fma.rn.f32x2 %0, %1, %2, %3;" : "=l"(d) : "l"(a), "l"(b), "l"(c));
    return d;
}
__device__ __forceinline__ ull pack2(float lo, float hi) {
    ull u;
    asm("mov.b64 %0, {%1, %2};" : "=l"(u) : "f"(lo), "f"(hi));
    return u;
}
__device__ __forceinline__ void unpack2(ull u, float& lo, float& hi) {
    asm("mov.b64 {%0, %1}, %2;" : "=f"(lo), "=f"(hi) : "l"(u));
}

__global__ void zero_cnt_kernel(int* __restrict__ cnt, int n4) {
    int i = blockIdx.x * blockDim.x + threadIdx.x;
    if (i < n4) reinterpret_cast<int4*>(cnt)[i] = make_int4(0, 0, 0, 0);
}

// ---------------- fused front kernel: 5 fills + 3 embeds ----------------

__device__ __forceinline__ void fill_body(
    const int* __restrict__ eg, int E, int off, int blockLocal,
    int* __restrict__ cnt, int* __restrict__ bucket) {
    int i0 = (blockLocal * 256 + (int)threadIdx.x) * 4;
    if (i0 >= E) return;
    int4 s4 = *reinterpret_cast<const int4*>(eg + i0);
    int4 d4 = *reinterpret_cast<const int4*>(eg + E + i0);
    int ss[4] = {s4.x, s4.y, s4.z, s4.w};
    int dd[4] = {d4.x, d4.y, d4.z, d4.w};
#pragma unroll
    for (int j = 0; j < 4; ++j) {
        int d = off + dd[j];
        int slot = atomicAdd(&cnt[d], 1);
        if (slot < CAP) bucket[(size_t)d * CAP + slot] = ss[j];
    }
}

// 8 nodes per warp: coalesced LDGs fetch 8*CIN inputs, distributed by
// compile-time shfl; W column + bias in registers (loaded once per warp).
template <int CIN>
__device__ __forceinline__ void embed_body(
    const float* __restrict__ x, const float* __restrict__ W,
    const float* __restrict__ bias, float* __restrict__ out,
    int warpInSeg, int tot /* BB*nNodes */, int lane) {
    int node0 = warpInSeg * 8;
    if (node0 >= tot) return;
    float Wr[CIN];
#pragma unroll
    for (int k = 0; k < CIN; ++k) Wr[k] = W[k * CC + lane];
    float bv = bias[lane];

    const float* xp = x + (size_t)node0 * CIN;
    long long rem = ((long long)tot - node0) * CIN;
    float r0 = 0.f, r1 = 0.f;
    if (lane < rem) r0 = xp[lane];
    if (CIN * 8 > 32 && 32 + lane < rem) r1 = xp[32 + lane];

#pragma unroll
    for (int j = 0; j < 8; ++j) {
        if (node0 + j >= tot) break;
        float acc = bv;
#pragma unroll
        for (int k = 0; k < CIN; ++k) {
            const int idx = j * CIN + k;
            float xv = (idx < 32) ? __shfl_sync(0xffffffffu, r0, idx)
                                  : __shfl_sync(0xffffffffu, r1, idx - 32);
            acc += xv * Wr[k];
        }
        out[(size_t)(node0 + j) * CC + lane] = acc > 0.f ? acc : 0.01f * acc;
    }
}

__global__ __launch_bounds__(256) void front_kernel(
    // fill: 5 edge lists, cumulative block ends fb1..fb5
    const int* fe, int Efe, const int* ev, int Eev, const int* ff, int Eff,
    const int* ef, int Eef, const int* ve, int Eve,
    int fb1, int fb2, int fb3, int fb4, int fb5,
    int* cnt, int* bucket,
    // embed: cumulative block ends (absolute) eb1, eb2
    const float* xF, const float* WF, const float* bF, float* oF,
    const float* xE, const float* WE, const float* bE, float* oE,
    const float* xV, const float* WV, const float* bV, float* oV,
    int eb1, int eb2) {
    int blk = blockIdx.x;
    int lane = threadIdx.x & 31, wip = threadIdx.x >> 5;
    if (blk < fb5) {
        const int* eg; int E; int off; int b0;
        if      (blk < fb1) { eg = fe; E = Efe; off = OFF_F2E; b0 = 0; }
        else if (blk < fb2) { eg = ev; E = Eev; off = OFF_E2V; b0 = fb1; }
        else if (blk < fb3) { eg = ff; E = Eff; off = OFF_FF;  b0 = fb2; }
        else if (blk < fb4) { eg = ef; E = Eef; off = OFF_E2F; b0 = fb3; }
        else                { eg = ve; E = Eve; off = OFF_V2E; b0 = fb4; }
        fill_body(eg, E, off, blk - b0, cnt, bucket);
    } else if (blk < eb1) {
        embed_body<4>(xF, WF, bF, oF, (blk - fb5) * 8 + wip, BB * NF, lane);
    } else if (blk < eb2) {
        embed_body<6>(xE, WE, bE, oE, (blk - eb1) * 8 + wip, BB * NE, lane);
    } else {
        embed_body<3>(xV, WV, bV, oV, (blk - eb2) * 8 + wip, BB * NV, lane);
    }
}

// ---------------- reduce body (compile-time strides) ----------------
// Block = 64 nodes; warp = 8 nodes as 4 PAIRS. One joint MLP pass per pair
// shares each W smem load across 2 nodes x 4 batches. Bucket row via one
// coalesced LDG + shfl; chain-head prefetch. Bias folded into acc init.

template <int NS, int ND>
__device__ __forceinline__ void reduce_body(
    const int* __restrict__ cnt, const int* __restrict__ bucket,
    const float* __restrict__ xs, const float* __restrict__ xd,
    const float* __restrict__ W, const float* __restrict__ bias,
    float* __restrict__ out, int blockLocal, int lane, int wip,
    ull (&sWp)[CC][CC], float2 (&stage)[2][8][BB][CC]) {
    for (int k = wip; k < CC; k += 8)
        sWp[k][lane] = pack2(W[k * CC + lane], W[(k + CC) * CC + lane]);
    __syncthreads();

    float bv = bias[lane];
    const size_t BS = (size_t)NS * CC;   // compile-time batch stride
    const float PINF = __int_as_float(0x7f800000);

    int dBase = blockLocal * 64 + wip * 8;

    int pdeg0 = cnt[dBase],     pdeg1 = cnt[dBase + 1];
    int pbkv0 = bucket[(size_t)dBase * CAP + lane];
    int pbkv1 = bucket[(size_t)(dBase + 1) * CAP + lane];

#pragma unroll 1
    for (int p = 0; p < 4; ++p) {
        int dA = dBase + 2 * p;
        int cdeg[2] = {pdeg0, pdeg1};
        int cbkv[2] = {pbkv0, pbkv1};
        if (p < 3) {
            pdeg0 = cnt[dA + 2];
            pdeg1 = cnt[dA + 3];
            pbkv0 = bucket[(size_t)(dA + 2) * CAP + lane];
            pbkv1 = bucket[(size_t)(dA + 3) * CAP + lane];
        }

        // ---- gather + stage both nodes of the pair ----
#pragma unroll
        for (int n = 0; n < 2; ++n) {
            int d = dA + n;
            int deg = cdeg[n] > CAP ? CAP : cdeg[n];
            int bkv = cbkv[n];

            float xv0 = xd[((size_t)0 * ND + d) * CC + lane];
            float xv1 = xd[((size_t)1 * ND + d) * CC + lane];
            float xv2 = xd[((size_t)2 * ND + d) * CC + lane];
            float xv3 = xd[((size_t)3 * ND + d) * CC + lane];

            float mn0 = PINF, mn1 = PINF, mn2 = PINF, mn3 = PINF;
            int i = 0;
            for (; i + 4 <= deg; i += 4) {
                int s0 = __shfl_sync(0xffffffffu, bkv, i);
                int s1 = __shfl_sync(0xffffffffu, bkv, i + 1);
                int s2 = __shfl_sync(0xffffffffu, bkv, i + 2);
                int s3 = __shfl_sync(0xffffffffu, bkv, i + 3);
                const float* p0 = xs + (size_t)s0 * CC + lane;
                const float* p1 = xs + (size_t)s1 * CC + lane;
                const float* p2 = xs + (size_t)s2 * CC + lane;
                const float* p3 = xs + (size_t)s3 * CC + lane;
                float a0 = p0[0],      a1 = p1[0],      a2 = p2[0],      a3 = p3[0];
                float b0 = p0[BS],     b1 = p1[BS],     b2 = p2[BS],     b3 = p3[BS];
                float c0 = p0[2 * BS], c1 = p1[2 * BS], c2 = p2[2 * BS], c3 = p3[2 * BS];
                float e0 = p0[3 * BS], e1 = p1[3 * BS], e2 = p2[3 * BS], e3 = p3[3 * BS];
                mn0 = fminf(mn0, fminf(fminf(a0, a1), fminf(a2, a3)));
                mn1 = fminf(mn1, fminf(fminf(b0, b1), fminf(b2, b3)));
                mn2 = fminf(mn2, fminf(fminf(c0, c1), fminf(c2, c3)));
                mn3 = fminf(mn3, fminf(fminf(e0, e1), fminf(e2, e3)));
            }
            for (; i < deg; ++i) {
                int s = __shfl_sync(0xffffffffu, bkv, i);
                const float* q = xs + (size_t)s * CC + lane;
                mn0 = fminf(mn0, q[0]);
                mn1 = fminf(mn1, q[BS]);
                mn2 = fminf(mn2, q[2 * BS]);
                mn3 = fminf(mn3, q[3 * BS]);
            }
            float mv0 = (__float_as_uint(mn0) == 0x7f800000u) ? 0.f : xv0 - mn0;
            float mv1 = (__float_as_uint(mn1) == 0x7f800000u) ? 0.f : xv1 - mn1;
            float mv2 = (__float_as_uint(mn2) == 0x7f800000u) ? 0.f : xv2 - mn2;
            float mv3 = (__float_as_uint(mn3) == 0x7f800000u) ? 0.f : xv3 - mn3;
            stage[n][wip][0][lane] = make_float2(xv0, mv0);
            stage[n][wip][1][lane] = make_float2(xv1, mv1);
            stage[n][wip][2][lane] = make_float2(xv2, mv2);
            stage[n][wip][3][lane] = make_float2(xv3, mv3);
        }
        __syncwarp();

        // ---- joint MLP: each W load feeds 2 nodes x 4 batches; bias in init ----
        ull acc[2][BB];
#pragma unroll
        for (int n = 0; n < 2; ++n)
#pragma unroll
            for (int b = 0; b < BB; ++b) acc[n][b] = pack2(bv, 0.f);
#pragma unroll
        for (int kt = 0; kt < CC; kt += 2) {
            ull w0 = sWp[kt][lane], w1 = sWp[kt + 1][lane];
#pragma unroll
            for (int n = 0; n < 2; ++n)
#pragma unroll
                for (int b = 0; b < BB; ++b) {
                    ulonglong2 h01 = *reinterpret_cast<const ulonglong2*>(
                        &stage[n][wip][b][kt]);
                    acc[n][b] = ffma2(h01.x, w0, acc[n][b]);
                    acc[n][b] = ffma2(h01.y, w1, acc[n][b]);
                }
        }

        // ---- epilogue (xv re-read from stage) ----
#pragma unroll
        for (int n = 0; n < 2; ++n)
#pragma unroll
            for (int b = 0; b < BB; ++b) {
                float lo, hi;
                unpack2(acc[n][b], lo, hi);
                float a = lo + hi;
                float xvr = stage[n][wip][b][lane].x;
                float o = xvr + (a > 0.f ? a : 0.01f * a);
                out[((size_t)b * ND + (dA + n)) * CC + lane] = o;
            }
        __syncwarp();
    }
}

// Phase B: F2E <NF,NE> | E2V <NE,NV> | FF <NF,NF>  — compile-time dispatch.
__global__ __launch_bounds__(256, 5) void phaseB_kernel(
    const int* cnt, const int* bucket,
    const float* xf0, const float* xe0, const float* xv0,
    const float* W1, const float* b1, float* o1,
    const float* W2, const float* b2, float* o2,
    const float* W3, const float* b3, float* o3) {
    __shared__ ull sWp[CC][CC];
    __shared__ __align__(16) float2 stage[2][8][BB][CC];
    int lane = threadIdx.x & 31, wip = threadIdx.x >> 5;
    int blk = blockIdx.x;
    constexpr int B1 = NE / 64, B2 = NV / 64;
    if (blk < B1)
        reduce_body<NF, NE>(cnt + OFF_F2E, bucket + (size_t)OFF_F2E * CAP,
                            xf0, xe0, W1, b1, o1, blk, lane, wip, sWp, stage);
    else if (blk < B1 + B2)
        reduce_body<NE, NV>(cnt + OFF_E2V, bucket + (size_t)OFF_E2V * CAP,
                            xe0, xv0, W2, b2, o2, blk - B1, lane, wip, sWp, stage);
    else
        reduce_body<NF, NF>(cnt + OFF_FF, bucket + (size_t)OFF_FF * CAP,
                            xf0, xf0, W3, b3, o3, blk - B1 - B2, lane, wip, sWp, stage);
}

// Phase C: E2F <NE,NF> | V2E <NV,NE>
__global__ __launch_bounds__(256, 5) void phaseC_kernel(
    const int* cnt, const int* bucket,
    const float* xe1, const float* xf1, const float* xv,
    const float* W1, const float* b1, float* o1,
    const float* W2, const float* b2, float* o2) {
    __shared__ ull sWp[CC][CC];
    __shared__ __align__(16) float2 stage[2][8][BB][CC];
    int lane = threadIdx.x & 31, wip = threadIdx.x >> 5;
    int blk = blockIdx.x;
    constexpr int B1 = NF / 64;
    if (blk < B1)
        reduce_body<NE, NF>(cnt + OFF_E2F, bucket + (size_t)OFF_E2F * CAP,
                            xe1, xf1, W1, b1, o1, blk, lane, wip, sWp, stage);
    else
        reduce_body<NV, NE>(cnt + OFF_V2E, bucket + (size_t)OFF_V2E * CAP,
                            xv, xe1, W2, b2, o2, blk - B1, lane, wip, sWp, stage);
}

static inline int cdiv(long long a, int b) { return (int)((a + b - 1) / b); }

extern "C" void kernel_launch(void* const* d_in, const int* in_sizes, int n_in,
                              void* d_out, int out_size) {
    const float* x_f = (const float*)d_in[0];
    const float* x_e = (const float*)d_in[1];
    const float* x_v = (const float*)d_in[2];
    // d_in[3] = index_id (identity arange; unused)
    const int* fe = (const int*)d_in[4];
    const int* ev = (const int*)d_in[5];
    const int* ff = (const int*)d_in[6];
    const int* ef = (const int*)d_in[7];
    const int* ve = (const int*)d_in[8];
    const float* Wf = (const float*)d_in[9];   const float* bf = (const float*)d_in[10];
    const float* We = (const float*)d_in[11];  const float* be = (const float*)d_in[12];
    const float* Wv = (const float*)d_in[13];  const float* bv = (const float*)d_in[14];
    const float* W_f2e = (const float*)d_in[15]; const float* b_f2e = (const float*)d_in[16];
    const float* W_e2v = (const float*)d_in[17]; const float* b_e2v = (const float*)d_in[18];
    const float* W_ff  = (const float*)d_in[19]; const float* b_ff  = (const float*)d_in[20];
    const float* W_e2f = (const float*)d_in[21]; const float* b_e2f = (const float*)d_in[22];
    const float* W_v2e = (const float*)d_in[23]; const float* b_v2e = (const float*)d_in[24];

    int E_fe = in_sizes[4] / 2, E_ev = in_sizes[5] / 2, E_ff = in_sizes[6] / 2,
        E_ef = in_sizes[7] / 2, E_ve = in_sizes[8] / 2;

    float* out_xf = (float*)d_out;
    float* out_xe = out_xf + (size_t)BB * NF * CC;
    float* out_xv = out_xe + (size_t)BB * NE * CC;

    float *xf0, *xe0, *xv0, *xe1, *xf1;
    int *cnt, *bucket;
    cudaGetSymbolAddress((void**)&xf0, g_xf0);
    cudaGetSymbolAddress((void**)&xe0, g_xe0);
    cudaGetSymbolAddress((void**)&xv0, g_xv0);
    cudaGetSymbolAddress((void**)&xe1, g_xe1);
    cudaGetSymbolAddress((void**)&xf1, g_xf1);
    cudaGetSymbolAddress((void**)&cnt, g_cnt);
    cudaGetSymbolAddress((void**)&bucket, g_bucket);

    const int TB = 256;

    // ---- 1. zero all counters ----
    zero_cnt_kernel<<<cdiv(CNT_TOT / 4, TB), TB>>>(cnt, CNT_TOT / 4);

    // ---- 2. fused front: 5 fills + 3 embeds in ONE launch ----
    int fb1 = cdiv(E_fe / 4, TB);
    int fb2 = fb1 + cdiv(E_ev / 4, TB);
    int fb3 = fb2 + cdiv(E_ff / 4, TB);
    int fb4 = fb3 + cdiv(E_ef / 4, TB);
    int fb5 = fb4 + cdiv(E_ve / 4, TB);
    int ebF = cdiv(BB * NF, 64), ebE = cdiv(BB * NE, 64), ebV = cdiv(BB * NV, 64);
    int eb1 = fb5 + ebF;
    int eb2 = eb1 + ebE;
    int frontTot = eb2 + ebV;
    front_kernel<<<frontTot, TB>>>(
        fe, E_fe, ev, E_ev, ff, E_ff, ef, E_ef, ve, E_ve,
        fb1, fb2, fb3, fb4, fb5, cnt, bucket,
        x_f, Wf, bf, xf0,
        x_e, We, be, xe0,
        x_v, Wv, bv, xv0,
        eb1, eb2);

    // ---- 3. Phase B: F2E + E2V + FF ----
    phaseB_kernel<<<NE / 64 + NV / 64 + NF / 64, 256>>>(
        cnt, bucket, xf0, xe0, xv0,
        W_f2e, b_f2e, xe1,
        W_e2v, b_e2v, out_xv,
        W_ff, b_ff, xf1);

    // ---- 4. Phase C: E2F + V2E ----
    phaseC_kernel<<<NF / 64 + NE / 64, 256>>>(
        cnt, bucket, xe1, xf1, out_xv,
        W_e2f, b_e2f, out_xf,
        W_v2e, b_v2e, out_xe);
}